// round 1
// baseline (speedup 1.0000x reference)
#include <cuda_runtime.h>
#include <math.h>

#define NF 64
#define KS 7
#define NC 51
#define LG 1001
#define NB 16
#define NH 256
#define NW 256
#define GP 262   /* NH + 2*3 padded adjoint grid */

// ---------------- scratch (static device globals; no runtime alloc) ----------------
__device__ float  d_wn [NF * 49];          // normalized weights
__device__ float  d_wnf[NF * 49];          // flipped normalized weights (for adjoint)
__device__ float2 d_tab2[NF * 1000];       // LUT pairs: (t[l], t[l+1])
__device__ float  d_lut[3];                // g0, gmax, invstep
__device__ float  d_phi[(size_t)NB * NF * NH * NW];  // 256 MB
__device__ float  d_g  [NB * GP * GP];               // padded adjoint grid

// ---------------- prep 1: normalize weights, LUT params ----------------
__global__ void prep_weights(const float* __restrict__ cw,
                             const float* __restrict__ sf,
                             const float* __restrict__ grid)
{
    int f = threadIdx.x;
    if (f < NF) {
        float s = 0.f;
        for (int k = 0; k < 49; ++k) s += cw[f * 49 + k];
        float mean = s / 49.0f;
        float ss = 0.f;
        for (int k = 0; k < 49; ++k) {
            float v = cw[f * 49 + k] - mean;
            ss += v * v;
        }
        float sc = sf[f] / sqrtf(ss);
        for (int k = 0; k < 49; ++k) {
            float v = (cw[f * 49 + k] - mean) * sc;
            d_wn[f * 49 + k] = v;
            int p = k / 7, q = k % 7;
            d_wnf[f * 49 + (6 - p) * 7 + (6 - q)] = v;
        }
    }
    if (threadIdx.x == 0) {
        d_lut[0] = grid[0];
        d_lut[1] = grid[LG - 1];
        d_lut[2] = 1.0f / (grid[1] - grid[0]);
    }
}

// ---------------- prep 2: build RBF LUT (pairs) ----------------
__global__ void prep_table(const float* __restrict__ rw,
                           const float* __restrict__ centers,
                           const float* __restrict__ grid)
{
    __shared__ float tl[LG];
    __shared__ float cs[NC];
    __shared__ float rs[NC];
    int f = blockIdx.x;
    int t = threadIdx.x;
    if (t < NC) { cs[t] = centers[t]; rs[t] = rw[f * NC + t]; }
    __syncthreads();
    for (int l = t; l < LG; l += blockDim.x) {
        float g = grid[l];
        float s = 0.f;
        #pragma unroll 1
        for (int c = 0; c < NC; ++c) {
            float dd = 0.25f * (g - cs[c]);
            s += rs[c] * expf(-0.5f * dd * dd);
        }
        tl[l] = s;
    }
    __syncthreads();
    for (int l = t; l < LG - 1; l += blockDim.x)
        d_tab2[f * 1000 + l] = make_float2(tl[l], tl[l + 1]);
}

// ---------------- kernel B: forward conv (sym pad) + LUT -> phi ----------------
// tile: 32 rows x 64 cols per block, 256 threads, micro-tile 2x4 per thread
__global__ void __launch_bounds__(256) fwd_kernel(const float* __restrict__ x)
{
    __shared__ float xs[38][71];
    __shared__ float ws[NF * 49];

    int b  = blockIdx.z;
    int i0 = blockIdx.y * 32;
    int j0 = blockIdx.x * 64;
    int tid = threadIdx.x;

    const float* xb = x + (size_t)b * NH * NW;

    // load x tile + halo with symmetric-pad index mapping
    for (int tpos = tid; tpos < 38 * 70; tpos += 256) {
        int r = tpos / 70, c = tpos % 70;
        int gi = i0 - 3 + r;
        int gj = j0 - 3 + c;
        gi = (gi < 0) ? (-1 - gi) : ((gi >= NH) ? (2 * NH - 1 - gi) : gi);
        gj = (gj < 0) ? (-1 - gj) : ((gj >= NW) ? (2 * NW - 1 - gj) : gj);
        xs[r][c] = xb[gi * NW + gj];
    }
    for (int tpos = tid; tpos < NF * 49; tpos += 256) ws[tpos] = d_wn[tpos];
    __syncthreads();

    float g0 = d_lut[0], gmax = d_lut[1], invstep = d_lut[2];

    int tx = tid & 15, ty = tid >> 4;
    int li = ty * 2;   // local row base
    int lj = tx * 4;   // local col base

    for (int f = 0; f < NF; ++f) {
        float acc[2][4] = {{0.f,0.f,0.f,0.f},{0.f,0.f,0.f,0.f}};
        const float* wf = ws + f * 49;
        #pragma unroll
        for (int rr = 0; rr < 8; ++rr) {
            float row[10];
            #pragma unroll
            for (int k = 0; k < 10; ++k) row[k] = xs[li + rr][lj + k];
            #pragma unroll
            for (int i = 0; i < 2; ++i) {
                int p = rr - i;
                if (p >= 0 && p < 7) {
                    #pragma unroll
                    for (int q = 0; q < 7; ++q) {
                        float wv = wf[p * 7 + q];
                        #pragma unroll
                        for (int j = 0; j < 4; ++j)
                            acc[i][j] = fmaf(wv, row[q + j], acc[i][j]);
                    }
                }
            }
        }
        // LUT (reference semantics) + vectorized store
        const float2* tf = d_tab2 + f * 1000;
        float* op = d_phi + ((((size_t)b * NF + f) * NH + (i0 + li)) * NW + (j0 + lj));
        #pragma unroll
        for (int i = 0; i < 2; ++i) {
            float4 o;
            float* ov = (float*)&o;
            #pragma unroll
            for (int j = 0; j < 4; ++j) {
                float v = acc[i][j];
                v = fminf(fmaxf(v, g0), gmax);
                float pos = (v - g0) * invstep;
                int idx = (int)floorf(pos);
                idx = idx < 0 ? 0 : (idx > 999 ? 999 : idx);
                float frac = pos - (float)idx;
                float2 tv = __ldg(tf + idx);
                ov[j] = tv.x * (1.0f - frac) + tv.y * frac;
            }
            *reinterpret_cast<float4*>(op + (size_t)i * NW) = o;
        }
    }
}

// ---------------- kernel C: adjoint conv, phi -> g_xp on padded grid ----------------
// tile: 32x32 per block over [0,GP)^2, 256 threads, micro-tile 2x2
__global__ void __launch_bounds__(256) bwd_kernel()
{
    __shared__ float ps[38][40];
    __shared__ float ws[NF * 49];

    int b  = blockIdx.z;
    int m0 = blockIdx.y * 32;
    int n0 = blockIdx.x * 32;
    int tid = threadIdx.x;

    for (int tpos = tid; tpos < NF * 49; tpos += 256) ws[tpos] = d_wnf[tpos];

    int tx = tid & 15, ty = tid >> 4;
    int li = ty * 2, lj = tx * 2;

    float acc[2][2] = {{0.f,0.f},{0.f,0.f}};
    const float* phib = d_phi + (size_t)b * NF * NH * NW;

    for (int f = 0; f < NF; ++f) {
        __syncthreads();
        const float* pf = phib + (size_t)f * NH * NW;
        for (int tpos = tid; tpos < 38 * 38; tpos += 256) {
            int r = tpos / 38, c = tpos % 38;
            int gi = m0 - 6 + r;
            int gj = n0 - 6 + c;
            float pv = 0.f;
            if (gi >= 0 && gi < NH && gj >= 0 && gj < NW)
                pv = pf[gi * NW + gj];
            ps[r][c] = pv;
        }
        __syncthreads();

        const float* wf = ws + f * 49;   // flipped weights: wf[u*7+v] = w[6-u][6-v]
        #pragma unroll
        for (int rr = 0; rr < 8; ++rr) {
            float row[8];
            #pragma unroll
            for (int k = 0; k < 8; ++k) row[k] = ps[li + rr][lj + k];
            #pragma unroll
            for (int i = 0; i < 2; ++i) {
                int u = rr - i;
                if (u >= 0 && u < 7) {
                    #pragma unroll
                    for (int vv = 0; vv < 7; ++vv) {
                        float wv = wf[u * 7 + vv];
                        #pragma unroll
                        for (int j = 0; j < 2; ++j)
                            acc[i][j] = fmaf(wv, row[vv + j], acc[i][j]);
                    }
                }
            }
        }
    }

    #pragma unroll
    for (int i = 0; i < 2; ++i)
        #pragma unroll
        for (int j = 0; j < 2; ++j) {
            int m = m0 + li + i, n = n0 + lj + j;
            if (m < GP && n < GP)
                d_g[((size_t)b * GP + m) * GP + n] = acc[i][j];
        }
}

// ---------------- kernel D: sym-pad fold + residual + Poisson prox ----------------
__global__ void finish_kernel(const float* __restrict__ input,
                              const float* __restrict__ noisy,
                              const float* __restrict__ a_cond,
                              float* __restrict__ out)
{
    int t = blockIdx.x * blockDim.x + threadIdx.x;
    if (t >= NB * NH * NW) return;
    int b   = t >> 16;
    int rem = t & 65535;
    int i = rem >> 8, j = rem & 255;

    const float* gb = d_g + (size_t)b * GP * GP;

    int mi[2], nj[2];
    int nm = 1, nn = 1;
    mi[0] = i + 3;
    nj[0] = j + 3;
    if (i < 3)       mi[nm++] = 2 - i;
    if (i >= NH - 3) mi[nm++] = 2 * NH + 2 - i;
    if (j < 3)       nj[nn++] = 2 - j;
    if (j >= NW - 3) nj[nn++] = 2 * NW + 2 - j;

    float r = 0.f;
    for (int a = 0; a < nm; ++a)
        for (int c = 0; c < nn; ++c)
            r += gb[mi[a] * GP + nj[c]];

    float av = a_cond[b];
    float z = input[t] - r;
    float d = z - av;
    out[t] = 0.5f * (d + sqrtf(d * d + 4.0f * av * noisy[t]));
}

// ---------------- launch ----------------
extern "C" void kernel_launch(void* const* d_in, const int* in_sizes, int n_in,
                              void* d_out, int out_size)
{
    const float* input   = (const float*)d_in[0];
    const float* noisy   = (const float*)d_in[1];
    const float* a_cond  = (const float*)d_in[2];
    const float* cw      = (const float*)d_in[3];
    const float* sf      = (const float*)d_in[4];
    const float* rw      = (const float*)d_in[5];
    const float* centers = (const float*)d_in[6];
    const float* grid    = (const float*)d_in[7];
    float* out = (float*)d_out;

    prep_weights<<<1, 64>>>(cw, sf, grid);
    prep_table<<<NF, 128>>>(rw, centers, grid);
    fwd_kernel<<<dim3(4, 8, NB), 256>>>(input);
    bwd_kernel<<<dim3(9, 9, NB), 256>>>();
    finish_kernel<<<(NB * NH * NW + 255) / 256, 256>>>(input, noisy, a_cond, out);
}

// round 3
// speedup vs baseline: 1.0579x; 1.0579x over previous
#include <cuda_runtime.h>
#include <stdint.h>
#include <math.h>

#define NF 64
#define KS 7
#define NC 51
#define LG 1001
#define NB 16
#define NH 256
#define NW 256
#define GP 262   /* NH + 2*3 padded adjoint grid */

// ---------------- scratch (static device globals; no runtime alloc) ----------------
__device__ float  d_wn [NF * 49];          // normalized weights
__device__ float  d_wnf[NF * 49];          // flipped normalized weights (for adjoint)
__device__ float2 d_tab2[NF * 1000];       // LUT pairs: (t[l], t[l+1])
__device__ float  d_lut[3];                // g0, gmax, invstep
__device__ float  d_phi[(size_t)NB * NF * NH * NW];  // 256 MB
__device__ float  d_g  [NB * GP * GP];               // padded adjoint grid
__device__ float  d_zerof = 0.0f;          // OOB source for cp.async

// ---------------- cp.async helpers ----------------
__device__ __forceinline__ void cp_async_f32(void* sdst, const void* gsrc) {
    unsigned int sa = (unsigned int)__cvta_generic_to_shared(sdst);
    asm volatile("cp.async.ca.shared.global [%0], [%1], 4;\n" :: "r"(sa), "l"(gsrc));
}
__device__ __forceinline__ void cp_commit() {
    asm volatile("cp.async.commit_group;\n");
}
__device__ __forceinline__ void cp_wait0() {
    asm volatile("cp.async.wait_group 0;\n");
}

// ---------------- prep 1: normalize weights, LUT params ----------------
__global__ void prep_weights(const float* __restrict__ cw,
                             const float* __restrict__ sf,
                             const float* __restrict__ grid)
{
    int f = threadIdx.x;
    if (f < NF) {
        float s = 0.f;
        for (int k = 0; k < 49; ++k) s += cw[f * 49 + k];
        float mean = s / 49.0f;
        float ss = 0.f;
        for (int k = 0; k < 49; ++k) {
            float v = cw[f * 49 + k] - mean;
            ss += v * v;
        }
        float sc = sf[f] / sqrtf(ss);
        for (int k = 0; k < 49; ++k) {
            float v = (cw[f * 49 + k] - mean) * sc;
            d_wn[f * 49 + k] = v;
            int p = k / 7, q = k % 7;
            d_wnf[f * 49 + (6 - p) * 7 + (6 - q)] = v;
        }
    }
    if (threadIdx.x == 0) {
        d_lut[0] = grid[0];
        d_lut[1] = grid[LG - 1];
        d_lut[2] = 1.0f / (grid[1] - grid[0]);
    }
}

// ---------------- prep 2: build RBF LUT (pairs) ----------------
__global__ void prep_table(const float* __restrict__ rw,
                           const float* __restrict__ centers,
                           const float* __restrict__ grid)
{
    __shared__ float tl[LG];
    __shared__ float cs[NC];
    __shared__ float rs[NC];
    int f = blockIdx.x;
    int t = threadIdx.x;
    if (t < NC) { cs[t] = centers[t]; rs[t] = rw[f * NC + t]; }
    __syncthreads();
    for (int l = t; l < LG; l += blockDim.x) {
        float g = grid[l];
        float s = 0.f;
        #pragma unroll 1
        for (int c = 0; c < NC; ++c) {
            float dd = 0.25f * (g - cs[c]);
            s += rs[c] * expf(-0.5f * dd * dd);
        }
        tl[l] = s;
    }
    __syncthreads();
    for (int l = t; l < LG - 1; l += blockDim.x)
        d_tab2[f * 1000 + l] = make_float2(tl[l], tl[l + 1]);
}

// ---------------- kernel B: forward conv (sym pad) + LUT -> phi ----------------
// tile: 32 rows x 64 cols per block, 256 threads, micro-tile 2x4 per thread
__global__ void __launch_bounds__(256) fwd_kernel(const float* __restrict__ x)
{
    __shared__ float xs[38][72];   // stride 72 -> 16B-aligned float4 rows
    __shared__ float ws[NF * 49];

    int b  = blockIdx.z;
    int i0 = blockIdx.y * 32;
    int j0 = blockIdx.x * 64;
    int tid = threadIdx.x;

    const float* xb = x + (size_t)b * NH * NW;

    // load x tile + halo with symmetric-pad index mapping
    for (int tpos = tid; tpos < 38 * 70; tpos += 256) {
        int r = tpos / 70, c = tpos - r * 70;
        int gi = i0 - 3 + r;
        int gj = j0 - 3 + c;
        gi = (gi < 0) ? (-1 - gi) : ((gi >= NH) ? (2 * NH - 1 - gi) : gi);
        gj = (gj < 0) ? (-1 - gj) : ((gj >= NW) ? (2 * NW - 1 - gj) : gj);
        xs[r][c] = xb[gi * NW + gj];
    }
    for (int tpos = tid; tpos < NF * 49; tpos += 256) ws[tpos] = d_wn[tpos];
    __syncthreads();

    float g0 = d_lut[0], gmax = d_lut[1], invstep = d_lut[2];

    int tx = tid & 15, ty = tid >> 4;
    int li = ty * 2;   // local row base
    int lj = tx * 4;   // local col base (multiple of 4 -> aligned)

    for (int f = 0; f < NF; ++f) {
        float acc[2][4] = {{0.f,0.f,0.f,0.f},{0.f,0.f,0.f,0.f}};
        const float* wf = ws + f * 49;
        #pragma unroll
        for (int rr = 0; rr < 8; ++rr) {
            float row[10];
            const float* rp = &xs[li + rr][lj];
            *reinterpret_cast<float4*>(&row[0]) = *reinterpret_cast<const float4*>(rp);
            *reinterpret_cast<float4*>(&row[4]) = *reinterpret_cast<const float4*>(rp + 4);
            *reinterpret_cast<float2*>(&row[8]) = *reinterpret_cast<const float2*>(rp + 8);
            #pragma unroll
            for (int i = 0; i < 2; ++i) {
                int p = rr - i;
                if (p >= 0 && p < 7) {
                    #pragma unroll
                    for (int q = 0; q < 7; ++q) {
                        float wv = wf[p * 7 + q];
                        #pragma unroll
                        for (int j = 0; j < 4; ++j)
                            acc[i][j] = fmaf(wv, row[q + j], acc[i][j]);
                    }
                }
            }
        }
        // LUT (reference semantics) + vectorized store
        const float2* tf = d_tab2 + f * 1000;
        float* op = d_phi + ((((size_t)b * NF + f) * NH + (i0 + li)) * NW + (j0 + lj));
        #pragma unroll
        for (int i = 0; i < 2; ++i) {
            float4 o;
            float* ov = (float*)&o;
            #pragma unroll
            for (int j = 0; j < 4; ++j) {
                float v = acc[i][j];
                v = fminf(fmaxf(v, g0), gmax);
                float pos = (v - g0) * invstep;
                int idx = (int)floorf(pos);
                idx = idx < 0 ? 0 : (idx > 999 ? 999 : idx);
                float frac = pos - (float)idx;
                float2 tv = __ldg(tf + idx);
                ov[j] = tv.x * (1.0f - frac) + tv.y * frac;
            }
            *reinterpret_cast<float4*>(op + (size_t)i * NW) = o;
        }
    }
}

// ---------------- kernel C: adjoint conv, phi -> g_xp on padded grid ----------------
// tile: 32 rows x 64 cols over [0,GP)^2, 256 threads, micro-tile 2x4,
// cp.async double-buffered phi tiles
__global__ void __launch_bounds__(256) bwd_kernel()
{
    __shared__ float ps[2][38][72];  // double buffer, stride 72 (aligned)
    __shared__ float ws[NF * 49];

    int b  = blockIdx.z;
    int m0 = blockIdx.y * 32;
    int n0 = blockIdx.x * 64;
    int tid = threadIdx.x;

    for (int tpos = tid; tpos < NF * 49; tpos += 256) ws[tpos] = d_wnf[tpos];

    int tx = tid & 15, ty = tid >> 4;
    int li = ty * 2, lj = tx * 4;

    float acc[2][4] = {{0.f,0.f,0.f,0.f},{0.f,0.f,0.f,0.f}};
    const float* phib = d_phi + (size_t)b * NF * NH * NW;

    // prologue: async fill buffer 0 with plane f=0
    {
        const float* pf = phib;
        for (int tpos = tid; tpos < 38 * 70; tpos += 256) {
            int r = tpos / 70, c = tpos - r * 70;
            int gi = m0 - 6 + r;
            int gj = n0 - 6 + c;
            bool inb = (gi >= 0) & (gi < NH) & (gj >= 0) & (gj < NW);
            const float* src = inb ? (pf + gi * NW + gj) : &d_zerof;
            cp_async_f32(&ps[0][r][c], src);
        }
        cp_commit();
    }

    int buf = 0;
    for (int f = 0; f < NF; ++f) {
        cp_wait0();
        __syncthreads();

        // prefetch next plane into the other buffer (overlaps with compute)
        if (f + 1 < NF) {
            const float* pf = phib + (size_t)(f + 1) * NH * NW;
            int ob = buf ^ 1;
            for (int tpos = tid; tpos < 38 * 70; tpos += 256) {
                int r = tpos / 70, c = tpos - r * 70;
                int gi = m0 - 6 + r;
                int gj = n0 - 6 + c;
                bool inb = (gi >= 0) & (gi < NH) & (gj >= 0) & (gj < NW);
                const float* src = inb ? (pf + gi * NW + gj) : &d_zerof;
                cp_async_f32(&ps[ob][r][c], src);
            }
            cp_commit();
        }

        const float* wf = ws + f * 49;   // flipped weights
        #pragma unroll
        for (int rr = 0; rr < 8; ++rr) {
            float row[10];
            const float* rp = &ps[buf][li + rr][lj];
            *reinterpret_cast<float4*>(&row[0]) = *reinterpret_cast<const float4*>(rp);
            *reinterpret_cast<float4*>(&row[4]) = *reinterpret_cast<const float4*>(rp + 4);
            *reinterpret_cast<float2*>(&row[8]) = *reinterpret_cast<const float2*>(rp + 8);
            #pragma unroll
            for (int i = 0; i < 2; ++i) {
                int u = rr - i;
                if (u >= 0 && u < 7) {
                    #pragma unroll
                    for (int vv = 0; vv < 7; ++vv) {
                        float wv = wf[u * 7 + vv];
                        #pragma unroll
                        for (int j = 0; j < 4; ++j)
                            acc[i][j] = fmaf(wv, row[vv + j], acc[i][j]);
                    }
                }
            }
        }
        buf ^= 1;
    }

    #pragma unroll
    for (int i = 0; i < 2; ++i)
        #pragma unroll
        for (int j = 0; j < 4; ++j) {
            int m = m0 + li + i, n = n0 + lj + j;
            if (m < GP && n < GP)
                d_g[((size_t)b * GP + m) * GP + n] = acc[i][j];
        }
}

// ---------------- kernel D: sym-pad fold + residual + Poisson prox ----------------
__global__ void finish_kernel(const float* __restrict__ input,
                              const float* __restrict__ noisy,
                              const float* __restrict__ a_cond,
                              float* __restrict__ out)
{
    int t = blockIdx.x * blockDim.x + threadIdx.x;
    if (t >= NB * NH * NW) return;
    int b   = t >> 16;
    int rem = t & 65535;
    int i = rem >> 8, j = rem & 255;

    const float* gb = d_g + (size_t)b * GP * GP;

    int mi[2], nj[2];
    int nm = 1, nn = 1;
    mi[0] = i + 3;
    nj[0] = j + 3;
    if (i < 3)       mi[nm++] = 2 - i;
    if (i >= NH - 3) mi[nm++] = 2 * NH + 2 - i;
    if (j < 3)       nj[nn++] = 2 - j;
    if (j >= NW - 3) nj[nn++] = 2 * NW + 2 - j;

    float r = 0.f;
    for (int a = 0; a < nm; ++a)
        for (int c = 0; c < nn; ++c)
            r += gb[mi[a] * GP + nj[c]];

    float av = a_cond[b];
    float z = input[t] - r;
    float d = z - av;
    out[t] = 0.5f * (d + sqrtf(d * d + 4.0f * av * noisy[t]));
}

// ---------------- launch ----------------
extern "C" void kernel_launch(void* const* d_in, const int* in_sizes, int n_in,
                              void* d_out, int out_size)
{
    const float* input   = (const float*)d_in[0];
    const float* noisy   = (const float*)d_in[1];
    const float* a_cond  = (const float*)d_in[2];
    const float* cw      = (const float*)d_in[3];
    const float* sf      = (const float*)d_in[4];
    const float* rw      = (const float*)d_in[5];
    const float* centers = (const float*)d_in[6];
    const float* grid    = (const float*)d_in[7];
    float* out = (float*)d_out;

    prep_weights<<<1, 64>>>(cw, sf, grid);
    prep_table<<<NF, 128>>>(rw, centers, grid);
    fwd_kernel<<<dim3(4, 8, NB), 256>>>(input);
    bwd_kernel<<<dim3(5, 9, NB), 256>>>();
    finish_kernel<<<(NB * NH * NW + 255) / 256, 256>>>(input, noisy, a_cond, out);
}

// round 4
// speedup vs baseline: 1.6967x; 1.6039x over previous
#include <cuda_runtime.h>
#include <stdint.h>
#include <math.h>

#define NF 64
#define NFC 32              /* filters per chunk */
#define KS 7
#define NC 51
#define LG 1001
#define NB 16
#define NH 256
#define NW 256
#define GP 262              /* NH + 2*3 padded adjoint grid */

// ---------------- scratch (static device globals; no runtime alloc) ----------------
__device__ float  d_wn [NF * 49];                    // normalized weights
__device__ float  d_wnf[NF * 49];                    // flipped normalized weights
__device__ float2 d_tab2[NF * 1000];                 // LUT pairs: (t[l], t[l+1])
__device__ float  d_lut[3];                          // g0, gmax, invstep
__device__ float  d_phi[(size_t)NB * NF * NH * NW];  // 256 MB
__device__ float  d_g  [2 * NB * GP * GP];           // per-chunk padded adjoint grids

// ---------------- cp.async helpers ----------------
__device__ __forceinline__ void cp_async16_z(void* sdst, const void* gsrc, int src_bytes) {
    unsigned int sa = (unsigned int)__cvta_generic_to_shared(sdst);
    asm volatile("cp.async.cg.shared.global [%0], [%1], 16, %2;\n"
                 :: "r"(sa), "l"(gsrc), "r"(src_bytes));
}
__device__ __forceinline__ void cp_commit() {
    asm volatile("cp.async.commit_group;\n");
}
__device__ __forceinline__ void cp_wait0() {
    asm volatile("cp.async.wait_group 0;\n");
}

// ---------------- prep 1: normalize weights, LUT params ----------------
__global__ void prep_weights(const float* __restrict__ cw,
                             const float* __restrict__ sf,
                             const float* __restrict__ grid)
{
    int f = threadIdx.x;
    if (f < NF) {
        float s = 0.f;
        for (int k = 0; k < 49; ++k) s += cw[f * 49 + k];
        float mean = s / 49.0f;
        float ss = 0.f;
        for (int k = 0; k < 49; ++k) {
            float v = cw[f * 49 + k] - mean;
            ss += v * v;
        }
        float sc = sf[f] / sqrtf(ss);
        for (int k = 0; k < 49; ++k) {
            float v = (cw[f * 49 + k] - mean) * sc;
            d_wn[f * 49 + k] = v;
            int p = k / 7, q = k % 7;
            d_wnf[f * 49 + (6 - p) * 7 + (6 - q)] = v;
        }
    }
    if (threadIdx.x == 0) {
        d_lut[0] = grid[0];
        d_lut[1] = grid[LG - 1];
        d_lut[2] = 1.0f / (grid[1] - grid[0]);
    }
}

// ---------------- prep 2: build RBF LUT (pairs) ----------------
__global__ void prep_table(const float* __restrict__ rw,
                           const float* __restrict__ centers,
                           const float* __restrict__ grid)
{
    __shared__ float tl[LG];
    __shared__ float cs[NC];
    __shared__ float rs[NC];
    int f = blockIdx.x;
    int t = threadIdx.x;
    if (t < NC) { cs[t] = centers[t]; rs[t] = rw[f * NC + t]; }
    __syncthreads();
    for (int l = t; l < LG; l += blockDim.x) {
        float g = grid[l];
        float s = 0.f;
        #pragma unroll 1
        for (int c = 0; c < NC; ++c) {
            float dd = 0.25f * (g - cs[c]);
            s += rs[c] * expf(-0.5f * dd * dd);
        }
        tl[l] = s;
    }
    __syncthreads();
    for (int l = t; l < LG - 1; l += blockDim.x)
        d_tab2[f * 1000 + l] = make_float2(tl[l], tl[l + 1]);
}

// ---------------- kernel B: forward conv (sym pad) + LUT -> phi ----------------
// tile: 32 rows x 64 cols, 256 threads, micro-tile 2x4, 32-filter chunk per block
__global__ void __launch_bounds__(256) fwd_kernel(const float* __restrict__ x)
{
    __shared__ float xs[38][72];
    __shared__ float ws[NFC * 49];

    int b  = blockIdx.z;
    int i0 = blockIdx.y * 32;
    int jt = blockIdx.x & 3;
    int fc = blockIdx.x >> 2;          // filter chunk 0/1
    int j0 = jt * 64;
    int f0 = fc * NFC;
    int tid = threadIdx.x;

    const float* xb = x + (size_t)b * NH * NW;

    for (int tpos = tid; tpos < 38 * 70; tpos += 256) {
        int r = tpos / 70, c = tpos - r * 70;
        int gi = i0 - 3 + r;
        int gj = j0 - 3 + c;
        gi = (gi < 0) ? (-1 - gi) : ((gi >= NH) ? (2 * NH - 1 - gi) : gi);
        gj = (gj < 0) ? (-1 - gj) : ((gj >= NW) ? (2 * NW - 1 - gj) : gj);
        xs[r][c] = xb[gi * NW + gj];
    }
    for (int tpos = tid; tpos < NFC * 49; tpos += 256) ws[tpos] = d_wn[f0 * 49 + tpos];
    __syncthreads();

    float g0 = d_lut[0], gmax = d_lut[1], invstep = d_lut[2];

    int tx = tid & 15, ty = tid >> 4;
    int li = ty * 2;
    int lj = tx * 4;

    for (int ff = 0; ff < NFC; ++ff) {
        int f = f0 + ff;
        float acc[2][4] = {{0.f,0.f,0.f,0.f},{0.f,0.f,0.f,0.f}};
        const float* wf = ws + ff * 49;
        #pragma unroll
        for (int rr = 0; rr < 8; ++rr) {
            float row[10];
            const float* rp = &xs[li + rr][lj];
            *reinterpret_cast<float4*>(&row[0]) = *reinterpret_cast<const float4*>(rp);
            *reinterpret_cast<float4*>(&row[4]) = *reinterpret_cast<const float4*>(rp + 4);
            *reinterpret_cast<float2*>(&row[8]) = *reinterpret_cast<const float2*>(rp + 8);
            #pragma unroll
            for (int i = 0; i < 2; ++i) {
                int p = rr - i;
                if (p >= 0 && p < 7) {
                    #pragma unroll
                    for (int q = 0; q < 7; ++q) {
                        float wv = wf[p * 7 + q];
                        #pragma unroll
                        for (int j = 0; j < 4; ++j)
                            acc[i][j] = fmaf(wv, row[q + j], acc[i][j]);
                    }
                }
            }
        }
        const float2* tf = d_tab2 + f * 1000;
        float* op = d_phi + ((((size_t)b * NF + f) * NH + (i0 + li)) * NW + (j0 + lj));
        #pragma unroll
        for (int i = 0; i < 2; ++i) {
            float4 o;
            float* ov = (float*)&o;
            #pragma unroll
            for (int j = 0; j < 4; ++j) {
                float v = acc[i][j];
                v = fminf(fmaxf(v, g0), gmax);
                float pos = (v - g0) * invstep;
                int idx = (int)floorf(pos);
                idx = idx < 0 ? 0 : (idx > 999 ? 999 : idx);
                float frac = pos - (float)idx;
                float2 tv = __ldg(tf + idx);
                ov[j] = tv.x * (1.0f - frac) + tv.y * frac;
            }
            *reinterpret_cast<float4*>(op + (size_t)i * NW) = o;
        }
    }
}

// ---------------- kernel C: adjoint conv, phi -> per-chunk g on padded grid ----------
// tile: 32 rows x 64 cols over [0,GP)^2, 256 threads, micro-tile 2x4,
// 16B zero-filling cp.async double-buffered phi tiles, 32-filter chunk per block
__global__ void __launch_bounds__(256) bwd_kernel()
{
    __shared__ float ps[2][38][84];   // cols 0..79 = gj in [n0-8, n0+72); stride 84
    __shared__ float ws[NFC * 49];

    int b  = blockIdx.z;
    int m0 = blockIdx.y * 32;
    int nt = blockIdx.x % 5;
    int fc = blockIdx.x / 5;          // filter chunk 0/1
    int n0 = nt * 64;
    int f0 = fc * NFC;
    int tid = threadIdx.x;

    for (int tpos = tid; tpos < NFC * 49; tpos += 256) ws[tpos] = d_wnf[f0 * 49 + tpos];

    int tx = tid & 15, ty = tid >> 4;
    int li = ty * 2, lj = tx * 4;

    float acc[2][4] = {{0.f,0.f,0.f,0.f},{0.f,0.f,0.f,0.f}};
    const float* phib = d_phi + ((size_t)b * NF + f0) * NH * NW;

    // fill: 38 rows x 20 float4, zero-fill OOB vectors (boundaries are float4-aligned)
    #define BWD_FILL(BUF, PF)                                                   \
        for (int tpos = tid; tpos < 38 * 20; tpos += 256) {                     \
            int r = tpos / 20, c4 = tpos - r * 20;                              \
            int gi = m0 - 6 + r;                                                \
            int gj = n0 - 8 + c4 * 4;                                           \
            bool inb = (gi >= 0) & (gi < NH) & (gj >= 0) & (gj < NW);           \
            const float* src = inb ? ((PF) + gi * NW + gj) : (PF);              \
            cp_async16_z(&ps[BUF][r][c4 * 4], src, inb ? 16 : 0);               \
        }

    BWD_FILL(0, phib)
    cp_commit();

    int buf = 0;
    for (int ff = 0; ff < NFC; ++ff) {
        cp_wait0();
        __syncthreads();

        if (ff + 1 < NFC) {
            const float* pf = phib + (size_t)(ff + 1) * NH * NW;
            int ob = buf ^ 1;
            BWD_FILL(ob, pf)
            cp_commit();
        }

        const float* wf = ws + ff * 49;
        #pragma unroll
        for (int rr = 0; rr < 8; ++rr) {
            float row[10];
            const float* rp = &ps[buf][li + rr][lj + 2];   // float2-aligned
            #pragma unroll
            for (int k = 0; k < 5; ++k)
                *reinterpret_cast<float2*>(&row[2 * k]) =
                    *reinterpret_cast<const float2*>(rp + 2 * k);
            #pragma unroll
            for (int i = 0; i < 2; ++i) {
                int u = rr - i;
                if (u >= 0 && u < 7) {
                    #pragma unroll
                    for (int vv = 0; vv < 7; ++vv) {
                        float wv = wf[u * 7 + vv];
                        #pragma unroll
                        for (int j = 0; j < 4; ++j)
                            acc[i][j] = fmaf(wv, row[vv + j], acc[i][j]);
                    }
                }
            }
        }
        buf ^= 1;
    }
    #undef BWD_FILL

    float* gout = d_g + (size_t)fc * NB * GP * GP + (size_t)b * GP * GP;
    #pragma unroll
    for (int i = 0; i < 2; ++i)
        #pragma unroll
        for (int j = 0; j < 4; ++j) {
            int m = m0 + li + i, n = n0 + lj + j;
            if (m < GP && n < GP)
                gout[m * GP + n] = acc[i][j];
        }
}

// ---------------- kernel D: sym-pad fold (both chunks) + residual + prox ----------
__global__ void finish_kernel(const float* __restrict__ input,
                              const float* __restrict__ noisy,
                              const float* __restrict__ a_cond,
                              float* __restrict__ out)
{
    int t = blockIdx.x * blockDim.x + threadIdx.x;
    if (t >= NB * NH * NW) return;
    int b   = t >> 16;
    int rem = t & 65535;
    int i = rem >> 8, j = rem & 255;

    const float* gb0 = d_g + (size_t)b * GP * GP;
    const float* gb1 = gb0 + (size_t)NB * GP * GP;

    int mi[2], nj[2];
    int nm = 1, nn = 1;
    mi[0] = i + 3;
    nj[0] = j + 3;
    if (i < 3)       mi[nm++] = 2 - i;
    if (i >= NH - 3) mi[nm++] = 2 * NH + 2 - i;
    if (j < 3)       nj[nn++] = 2 - j;
    if (j >= NW - 3) nj[nn++] = 2 * NW + 2 - j;

    float r = 0.f;
    for (int a = 0; a < nm; ++a)
        for (int c = 0; c < nn; ++c) {
            int off = mi[a] * GP + nj[c];
            r += gb0[off] + gb1[off];
        }

    float av = a_cond[b];
    float z = input[t] - r;
    float d = z - av;
    out[t] = 0.5f * (d + sqrtf(d * d + 4.0f * av * noisy[t]));
}

// ---------------- launch ----------------
extern "C" void kernel_launch(void* const* d_in, const int* in_sizes, int n_in,
                              void* d_out, int out_size)
{
    const float* input   = (const float*)d_in[0];
    const float* noisy   = (const float*)d_in[1];
    const float* a_cond  = (const float*)d_in[2];
    const float* cw      = (const float*)d_in[3];
    const float* sf      = (const float*)d_in[4];
    const float* rw      = (const float*)d_in[5];
    const float* centers = (const float*)d_in[6];
    const float* grid    = (const float*)d_in[7];
    float* out = (float*)d_out;

    prep_weights<<<1, 64>>>(cw, sf, grid);
    prep_table<<<NF, 128>>>(rw, centers, grid);
    fwd_kernel<<<dim3(8, 8, NB), 256>>>(input);      // 4 j-tiles x 2 f-chunks
    bwd_kernel<<<dim3(10, 9, NB), 256>>>();          // 5 n-tiles x 2 f-chunks
    finish_kernel<<<(NB * NH * NW + 255) / 256, 256>>>(input, noisy, a_cond, out);
}

// round 5
// speedup vs baseline: 1.7077x; 1.0065x over previous
#include <cuda_runtime.h>
#include <stdint.h>
#include <math.h>

#define NF 64
#define NFC 32              /* filters per chunk */
#define NC 51
#define LG 1001
#define NB 16
#define NH 256
#define NW 256
#define GP 262              /* NH + 2*3 padded adjoint grid */

// ---------------- scratch ----------------
__device__ float  d_wn [NF * 49];
__device__ float  d_wnf[NF * 49];
__device__ float2 d_tab2[NF * 1000];
__device__ float  d_lut[3];
__device__ float  d_phi[(size_t)NB * NF * NH * NW];
__device__ float  d_g  [2 * NB * GP * GP];

// ---------------- cp.async helpers ----------------
__device__ __forceinline__ void cp_async16_z(void* sdst, const void* gsrc, int src_bytes) {
    unsigned int sa = (unsigned int)__cvta_generic_to_shared(sdst);
    asm volatile("cp.async.cg.shared.global [%0], [%1], 16, %2;\n"
                 :: "r"(sa), "l"(gsrc), "r"(src_bytes));
}
__device__ __forceinline__ void cp_commit() { asm volatile("cp.async.commit_group;\n"); }
__device__ __forceinline__ void cp_wait0()  { asm volatile("cp.async.wait_group 0;\n"); }

// ---------------- prep 1 ----------------
__global__ void prep_weights(const float* __restrict__ cw,
                             const float* __restrict__ sf,
                             const float* __restrict__ grid)
{
    int f = threadIdx.x;
    if (f < NF) {
        float s = 0.f;
        for (int k = 0; k < 49; ++k) s += cw[f * 49 + k];
        float mean = s / 49.0f;
        float ss = 0.f;
        for (int k = 0; k < 49; ++k) {
            float v = cw[f * 49 + k] - mean;
            ss += v * v;
        }
        float sc = sf[f] / sqrtf(ss);
        for (int k = 0; k < 49; ++k) {
            float v = (cw[f * 49 + k] - mean) * sc;
            d_wn[f * 49 + k] = v;
            int p = k / 7, q = k % 7;
            d_wnf[f * 49 + (6 - p) * 7 + (6 - q)] = v;
        }
    }
    if (threadIdx.x == 0) {
        d_lut[0] = grid[0];
        d_lut[1] = grid[LG - 1];
        d_lut[2] = 1.0f / (grid[1] - grid[0]);
    }
}

// ---------------- prep 2 ----------------
__global__ void prep_table(const float* __restrict__ rw,
                           const float* __restrict__ centers,
                           const float* __restrict__ grid)
{
    __shared__ float tl[LG];
    __shared__ float cs[NC];
    __shared__ float rs[NC];
    int f = blockIdx.x;
    int t = threadIdx.x;
    if (t < NC) { cs[t] = centers[t]; rs[t] = rw[f * NC + t]; }
    __syncthreads();
    for (int l = t; l < LG; l += blockDim.x) {
        float g = grid[l];
        float s = 0.f;
        #pragma unroll 1
        for (int c = 0; c < NC; ++c) {
            float dd = 0.25f * (g - cs[c]);
            s += rs[c] * expf(-0.5f * dd * dd);
        }
        tl[l] = s;
    }
    __syncthreads();
    for (int l = t; l < LG - 1; l += blockDim.x)
        d_tab2[f * 1000 + l] = make_float2(tl[l], tl[l + 1]);
}

// row loaders (16B-aligned variants)
#define LOADROW_A0(DST, SRC) do {                                              \
    *reinterpret_cast<float4*>(&(DST)[0])  = *reinterpret_cast<const float4*>((SRC));      \
    *reinterpret_cast<float4*>(&(DST)[4])  = *reinterpret_cast<const float4*>((SRC) + 4);  \
    *reinterpret_cast<float4*>(&(DST)[8])  = *reinterpret_cast<const float4*>((SRC) + 8);  \
    *reinterpret_cast<float2*>(&(DST)[12]) = *reinterpret_cast<const float2*>((SRC) + 12); \
} while (0)
#define LOADROW_A2(DST, SRC) do {                                              \
    *reinterpret_cast<float2*>(&(DST)[0])  = *reinterpret_cast<const float2*>((SRC));      \
    *reinterpret_cast<float4*>(&(DST)[2])  = *reinterpret_cast<const float4*>((SRC) + 2);  \
    *reinterpret_cast<float4*>(&(DST)[6])  = *reinterpret_cast<const float4*>((SRC) + 6);  \
    *reinterpret_cast<float4*>(&(DST)[10]) = *reinterpret_cast<const float4*>((SRC) + 10); \
} while (0)

// ---------------- kernel B: forward conv + LUT -> phi ----------------
// 128 threads, tile 32x64, micro-tile 2x8, weight-in-register p-loop
__global__ void __launch_bounds__(128) fwd_kernel(const float* __restrict__ x)
{
    __shared__ float xs[38][72];
    __shared__ float ws[NFC * 49];

    int b  = blockIdx.z;
    int i0 = blockIdx.y * 32;
    int jt = blockIdx.x & 3;
    int fc = blockIdx.x >> 2;
    int j0 = jt * 64;
    int f0 = fc * NFC;
    int tid = threadIdx.x;

    const float* xb = x + (size_t)b * NH * NW;

    for (int tpos = tid; tpos < 38 * 70; tpos += 128) {
        int r = tpos / 70, c = tpos - r * 70;
        int gi = i0 - 3 + r;
        int gj = j0 - 3 + c;
        gi = (gi < 0) ? (-1 - gi) : ((gi >= NH) ? (2 * NH - 1 - gi) : gi);
        gj = (gj < 0) ? (-1 - gj) : ((gj >= NW) ? (2 * NW - 1 - gj) : gj);
        xs[r][c] = xb[gi * NW + gj];
    }
    for (int tpos = tid; tpos < NFC * 49; tpos += 128) ws[tpos] = d_wn[f0 * 49 + tpos];
    __syncthreads();

    float g0 = d_lut[0], gmax = d_lut[1], invstep = d_lut[2];

    int tx = tid & 7, ty = tid >> 3;
    int li = ty * 2;
    int lj = tx * 8;

    for (int ff = 0; ff < NFC; ++ff) {
        int f = f0 + ff;
        const float* wf = ws + ff * 49;
        float acc[2][8];
        #pragma unroll
        for (int i = 0; i < 2; ++i)
            #pragma unroll
            for (int j = 0; j < 8; ++j) acc[i][j] = 0.f;

        float rows[2][14];
        LOADROW_A0(rows[0], &xs[li][lj]);
        #pragma unroll
        for (int p = 0; p < 7; ++p) {
            LOADROW_A0(rows[(p & 1) ^ 1], &xs[li + p + 1][lj]);
            float w[7];
            #pragma unroll
            for (int q = 0; q < 7; ++q) w[q] = wf[p * 7 + q];
            const float* rA = rows[p & 1];
            const float* rB = rows[(p & 1) ^ 1];
            #pragma unroll
            for (int q = 0; q < 7; ++q)
                #pragma unroll
                for (int j = 0; j < 8; ++j) {
                    acc[0][j] = fmaf(w[q], rA[q + j], acc[0][j]);
                    acc[1][j] = fmaf(w[q], rB[q + j], acc[1][j]);
                }
        }

        const float2* tf = d_tab2 + f * 1000;
        float* op = d_phi + ((((size_t)b * NF + f) * NH + (i0 + li)) * NW + (j0 + lj));
        #pragma unroll
        for (int i = 0; i < 2; ++i) {
            float o[8];
            #pragma unroll
            for (int j = 0; j < 8; ++j) {
                float v = acc[i][j];
                v = fminf(fmaxf(v, g0), gmax);
                float pos = (v - g0) * invstep;
                int idx = (int)floorf(pos);
                idx = idx < 0 ? 0 : (idx > 999 ? 999 : idx);
                float frac = pos - (float)idx;
                float2 tv = __ldg(tf + idx);
                o[j] = tv.x * (1.0f - frac) + tv.y * frac;
            }
            float* dst = op + (size_t)i * NW;
            *reinterpret_cast<float4*>(dst)     = *reinterpret_cast<float4*>(&o[0]);
            *reinterpret_cast<float4*>(dst + 4) = *reinterpret_cast<float4*>(&o[4]);
        }
    }
}

// ---------------- kernel C: adjoint conv -> per-chunk g ----------------
// 128 threads, tile 32x64 on padded grid, micro-tile 2x8, cp.async double buffer
__global__ void __launch_bounds__(128) bwd_kernel()
{
    __shared__ float ps[2][38][84];   // col c <-> gj = n0 - 8 + c; reads use cols 2..71
    __shared__ float ws[NFC * 49];

    int b  = blockIdx.z;
    int m0 = blockIdx.y * 32;
    int nt = blockIdx.x % 5;
    int fc = blockIdx.x / 5;
    int n0 = nt * 64;
    int f0 = fc * NFC;
    int tid = threadIdx.x;

    for (int tpos = tid; tpos < NFC * 49; tpos += 128) ws[tpos] = d_wnf[f0 * 49 + tpos];

    int tx = tid & 7, ty = tid >> 3;
    int li = ty * 2, lj = tx * 8;

    float acc[2][8];
    #pragma unroll
    for (int i = 0; i < 2; ++i)
        #pragma unroll
        for (int j = 0; j < 8; ++j) acc[i][j] = 0.f;

    const float* phib = d_phi + ((size_t)b * NF + f0) * NH * NW;

    #define BWD_FILL(BUF, PF)                                                   \
        for (int tpos = tid; tpos < 38 * 20; tpos += 128) {                     \
            int r = tpos / 20, c4 = tpos - r * 20;                              \
            int gi = m0 - 6 + r;                                                \
            int gj = n0 - 8 + c4 * 4;                                           \
            bool inb = (gi >= 0) & (gi < NH) & (gj >= 0) & (gj < NW);           \
            const float* src = inb ? ((PF) + gi * NW + gj) : (PF);              \
            cp_async16_z(&ps[BUF][r][c4 * 4], src, inb ? 16 : 0);               \
        }

    BWD_FILL(0, phib)
    cp_commit();

    int buf = 0;
    for (int ff = 0; ff < NFC; ++ff) {
        cp_wait0();
        __syncthreads();

        if (ff + 1 < NFC) {
            const float* pf = phib + (size_t)(ff + 1) * NH * NW;
            int ob = buf ^ 1;
            BWD_FILL(ob, pf)
            cp_commit();
        }

        const float* wf = ws + ff * 49;
        float rows[2][14];
        LOADROW_A2(rows[0], &ps[buf][li][lj + 2]);
        #pragma unroll
        for (int p = 0; p < 7; ++p) {
            LOADROW_A2(rows[(p & 1) ^ 1], &ps[buf][li + p + 1][lj + 2]);
            float w[7];
            #pragma unroll
            for (int q = 0; q < 7; ++q) w[q] = wf[p * 7 + q];
            const float* rA = rows[p & 1];
            const float* rB = rows[(p & 1) ^ 1];
            #pragma unroll
            for (int q = 0; q < 7; ++q)
                #pragma unroll
                for (int j = 0; j < 8; ++j) {
                    acc[0][j] = fmaf(w[q], rA[q + j], acc[0][j]);
                    acc[1][j] = fmaf(w[q], rB[q + j], acc[1][j]);
                }
        }
        buf ^= 1;
    }
    #undef BWD_FILL

    float* gout = d_g + (size_t)fc * NB * GP * GP + (size_t)b * GP * GP;
    #pragma unroll
    for (int i = 0; i < 2; ++i)
        #pragma unroll
        for (int j = 0; j < 8; ++j) {
            int m = m0 + li + i, n = n0 + lj + j;
            if (m < GP && n < GP)
                gout[m * GP + n] = acc[i][j];
        }
}

// ---------------- kernel D: fold + residual + prox ----------------
__global__ void finish_kernel(const float* __restrict__ input,
                              const float* __restrict__ noisy,
                              const float* __restrict__ a_cond,
                              float* __restrict__ out)
{
    int t = blockIdx.x * blockDim.x + threadIdx.x;
    if (t >= NB * NH * NW) return;
    int b   = t >> 16;
    int rem = t & 65535;
    int i = rem >> 8, j = rem & 255;

    const float* gb0 = d_g + (size_t)b * GP * GP;
    const float* gb1 = gb0 + (size_t)NB * GP * GP;

    int mi[2], nj[2];
    int nm = 1, nn = 1;
    mi[0] = i + 3;
    nj[0] = j + 3;
    if (i < 3)       mi[nm++] = 2 - i;
    if (i >= NH - 3) mi[nm++] = 2 * NH + 2 - i;
    if (j < 3)       nj[nn++] = 2 - j;
    if (j >= NW - 3) nj[nn++] = 2 * NW + 2 - j;

    float r = 0.f;
    for (int a = 0; a < nm; ++a)
        for (int c = 0; c < nn; ++c) {
            int off = mi[a] * GP + nj[c];
            r += gb0[off] + gb1[off];
        }

    float av = a_cond[b];
    float z = input[t] - r;
    float d = z - av;
    out[t] = 0.5f * (d + sqrtf(d * d + 4.0f * av * noisy[t]));
}

// ---------------- launch ----------------
extern "C" void kernel_launch(void* const* d_in, const int* in_sizes, int n_in,
                              void* d_out, int out_size)
{
    const float* input   = (const float*)d_in[0];
    const float* noisy   = (const float*)d_in[1];
    const float* a_cond  = (const float*)d_in[2];
    const float* cw      = (const float*)d_in[3];
    const float* sf      = (const float*)d_in[4];
    const float* rw      = (const float*)d_in[5];
    const float* centers = (const float*)d_in[6];
    const float* grid    = (const float*)d_in[7];
    float* out = (float*)d_out;

    prep_weights<<<1, 64>>>(cw, sf, grid);
    prep_table<<<NF, 128>>>(rw, centers, grid);
    fwd_kernel<<<dim3(8, 8, NB), 128>>>(input);
    bwd_kernel<<<dim3(10, 9, NB), 128>>>();
    finish_kernel<<<(NB * NH * NW + 255) / 256, 256>>>(input, noisy, a_cond, out);
}

// round 7
// speedup vs baseline: 1.8702x; 1.0952x over previous
#include <cuda_runtime.h>
#include <stdint.h>
#include <math.h>

#define NF 64
#define NFC 32              /* filters per chunk */
#define NC 51
#define LG 1001
#define NB 16
#define NH 256
#define NW 256
#define GP 262              /* NH + 2*3 padded adjoint grid */

// ---------------- scratch ----------------
__device__ float  d_wn [NF * 49];
__device__ float  d_wnf[NF * 49];
__device__ float2 d_tab2[NF * 1000];
__device__ float  d_lut[3];
__device__ float  d_phi[(size_t)NB * NF * NH * NW];
__device__ float  d_g  [2 * NB * GP * GP];

// ---------------- cp.async helpers ----------------
__device__ __forceinline__ void cp_async16_z(void* sdst, const void* gsrc, int src_bytes) {
    unsigned int sa = (unsigned int)__cvta_generic_to_shared(sdst);
    asm volatile("cp.async.cg.shared.global [%0], [%1], 16, %2;\n"
                 :: "r"(sa), "l"(gsrc), "r"(src_bytes));
}
__device__ __forceinline__ void cp_commit() { asm volatile("cp.async.commit_group;\n"); }
__device__ __forceinline__ void cp_wait0()  { asm volatile("cp.async.wait_group 0;\n"); }

// ---------------- prep 1 ----------------
__global__ void prep_weights(const float* __restrict__ cw,
                             const float* __restrict__ sf,
                             const float* __restrict__ grid)
{
    int f = threadIdx.x;
    if (f < NF) {
        float s = 0.f;
        for (int k = 0; k < 49; ++k) s += cw[f * 49 + k];
        float mean = s / 49.0f;
        float ss = 0.f;
        for (int k = 0; k < 49; ++k) {
            float v = cw[f * 49 + k] - mean;
            ss += v * v;
        }
        float sc = sf[f] / sqrtf(ss);
        for (int k = 0; k < 49; ++k) {
            float v = (cw[f * 49 + k] - mean) * sc;
            d_wn[f * 49 + k] = v;
            int p = k / 7, q = k % 7;
            d_wnf[f * 49 + (6 - p) * 7 + (6 - q)] = v;
        }
    }
    if (threadIdx.x == 0) {
        d_lut[0] = grid[0];
        d_lut[1] = grid[LG - 1];
        d_lut[2] = 1.0f / (grid[1] - grid[0]);
    }
}

// ---------------- prep 2 ----------------
__global__ void prep_table(const float* __restrict__ rw,
                           const float* __restrict__ centers,
                           const float* __restrict__ grid)
{
    __shared__ float tl[LG];
    __shared__ float cs[NC];
    __shared__ float rs[NC];
    int f = blockIdx.x;
    int t = threadIdx.x;
    if (t < NC) { cs[t] = centers[t]; rs[t] = rw[f * NC + t]; }
    __syncthreads();
    for (int l = t; l < LG; l += blockDim.x) {
        float g = grid[l];
        float s = 0.f;
        #pragma unroll 1
        for (int c = 0; c < NC; ++c) {
            float dd = 0.25f * (g - cs[c]);
            s += rs[c] * expf(-0.5f * dd * dd);
        }
        tl[l] = s;
    }
    __syncthreads();
    for (int l = t; l < LG - 1; l += blockDim.x)
        d_tab2[f * 1000 + l] = make_float2(tl[l], tl[l + 1]);
}

// vertical stencil accumulate: one input smem row (8 floats from an 8B-aligned
// pointer) feeds output rows i with p = t0 - i in [0,7). t0 and the i-loop are
// compile-time after unrolling, so the guard folds away.
__device__ __forceinline__ void stencil_row(const float* __restrict__ src, int t0,
                                            const float* __restrict__ w,
                                            float acc[8][2])
{
    float seg[8];
    *reinterpret_cast<float2*>(&seg[0]) = *reinterpret_cast<const float2*>(src);
    *reinterpret_cast<float2*>(&seg[2]) = *reinterpret_cast<const float2*>(src + 2);
    *reinterpret_cast<float2*>(&seg[4]) = *reinterpret_cast<const float2*>(src + 4);
    *reinterpret_cast<float2*>(&seg[6]) = *reinterpret_cast<const float2*>(src + 6);
    #pragma unroll
    for (int i = 0; i < 8; ++i) {
        int p = t0 - i;
        if (p >= 0 && p < 7) {
            #pragma unroll
            for (int q = 0; q < 7; ++q) {
                acc[i][0] = fmaf(w[p * 7 + q], seg[q],     acc[i][0]);
                acc[i][1] = fmaf(w[p * 7 + q], seg[q + 1], acc[i][1]);
            }
        }
    }
}

// ---------------- kernel B: forward conv + LUT -> phi ----------------
// 128 threads, tile 32x64, micro-tile 8 rows x 2 cols (warp = contiguous row segment)
__global__ void __launch_bounds__(128) fwd_kernel(const float* __restrict__ x)
{
    __shared__ float xs[38][72];
    __shared__ float ws[NFC * 49];

    int b  = blockIdx.z;
    int i0 = blockIdx.y * 32;
    int jt = blockIdx.x & 3;
    int fc = blockIdx.x >> 2;
    int j0 = jt * 64;
    int f0 = fc * NFC;
    int tid = threadIdx.x;

    const float* xb = x + (size_t)b * NH * NW;

    for (int tpos = tid; tpos < 38 * 70; tpos += 128) {
        int r = tpos / 70, c = tpos - r * 70;
        int gi = i0 - 3 + r;
        int gj = j0 - 3 + c;
        gi = (gi < 0) ? (-1 - gi) : ((gi >= NH) ? (2 * NH - 1 - gi) : gi);
        gj = (gj < 0) ? (-1 - gj) : ((gj >= NW) ? (2 * NW - 1 - gj) : gj);
        xs[r][c] = xb[gi * NW + gj];
    }
    for (int tpos = tid; tpos < NFC * 49; tpos += 128) ws[tpos] = d_wn[f0 * 49 + tpos];
    __syncthreads();

    float g0 = d_lut[0], gmax = d_lut[1], invstep = d_lut[2];

    int lane = tid & 31, wrp = tid >> 5;
    int li = wrp * 8;       // output row base in tile
    int lj = lane * 2;      // output col base in tile

    for (int ff = 0; ff < NFC; ++ff) {
        int f = f0 + ff;
        float w[49];
        #pragma unroll
        for (int k = 0; k < 49; ++k) w[k] = ws[ff * 49 + k];

        float acc[8][2];
        #pragma unroll
        for (int i = 0; i < 8; ++i) { acc[i][0] = 0.f; acc[i][1] = 0.f; }

        #pragma unroll
        for (int t0 = 0; t0 < 14; ++t0)
            stencil_row(&xs[li + t0][lj], t0, w, acc);

        const float2* tf = d_tab2 + f * 1000;
        float* op = d_phi + ((((size_t)b * NF + f) * NH + (i0 + li)) * NW + (j0 + lj));
        #pragma unroll
        for (int i = 0; i < 8; ++i) {
            float2 o;
            float v0 = fminf(fmaxf(acc[i][0], g0), gmax);
            float v1 = fminf(fmaxf(acc[i][1], g0), gmax);
            float pos0 = (v0 - g0) * invstep;
            float pos1 = (v1 - g0) * invstep;
            int idx0 = (int)floorf(pos0); idx0 = idx0 < 0 ? 0 : (idx0 > 999 ? 999 : idx0);
            int idx1 = (int)floorf(pos1); idx1 = idx1 < 0 ? 0 : (idx1 > 999 ? 999 : idx1);
            float fr0 = pos0 - (float)idx0;
            float fr1 = pos1 - (float)idx1;
            float2 tv0 = __ldg(tf + idx0);
            float2 tv1 = __ldg(tf + idx1);
            o.x = tv0.x * (1.0f - fr0) + tv0.y * fr0;
            o.y = tv1.x * (1.0f - fr1) + tv1.y * fr1;
            *reinterpret_cast<float2*>(op + (size_t)i * NW) = o;
        }
    }
}

// ---------------- kernel C: adjoint conv -> per-chunk g ----------------
// 128 threads, tile 32x64 on padded grid, micro-tile 8x2, cp.async double buffer
__global__ void __launch_bounds__(128) bwd_kernel()
{
    __shared__ float ps[2][38][84];   // col c <-> gj = n0 - 8 + c
    __shared__ float ws[NFC * 49];

    int b  = blockIdx.z;
    int m0 = blockIdx.y * 32;
    int nt = blockIdx.x % 5;
    int fc = blockIdx.x / 5;
    int n0 = nt * 64;
    int f0 = fc * NFC;
    int tid = threadIdx.x;

    for (int tpos = tid; tpos < NFC * 49; tpos += 128) ws[tpos] = d_wnf[f0 * 49 + tpos];

    int lane = tid & 31, wrp = tid >> 5;
    int li = wrp * 8;
    int lj = lane * 2;

    float acc[8][2];
    #pragma unroll
    for (int i = 0; i < 8; ++i) { acc[i][0] = 0.f; acc[i][1] = 0.f; }

    const float* phib = d_phi + ((size_t)b * NF + f0) * NH * NW;

    #define BWD_FILL(BUF, PF)                                                   \
        for (int tpos = tid; tpos < 38 * 20; tpos += 128) {                     \
            int r = tpos / 20, c4 = tpos - r * 20;                              \
            int gi = m0 - 6 + r;                                                \
            int gj = n0 - 8 + c4 * 4;                                           \
            bool inb = (gi >= 0) & (gi < NH) & (gj >= 0) & (gj < NW);           \
            const float* src = inb ? ((PF) + gi * NW + gj) : (PF);              \
            cp_async16_z(&ps[BUF][r][c4 * 4], src, inb ? 16 : 0);               \
        }

    BWD_FILL(0, phib)
    cp_commit();

    int buf = 0;
    for (int ff = 0; ff < NFC; ++ff) {
        cp_wait0();
        __syncthreads();

        if (ff + 1 < NFC) {
            const float* pf = phib + (size_t)(ff + 1) * NH * NW;
            int ob = buf ^ 1;
            BWD_FILL(ob, pf)
            cp_commit();
        }

        float w[49];
        #pragma unroll
        for (int k = 0; k < 49; ++k) w[k] = ws[ff * 49 + k];

        // g[m][n] = sum_{u,v} wnf[u][v] phi[m-6+u][n-6+v]
        // smem row r = gi-(m0-6): out row li+i needs r = li+i..li+i+6 -> t0 = 0..13
        // smem col c = gj-(n0-8): out col lj+j needs floats lj+2 .. lj+9
        #pragma unroll
        for (int t0 = 0; t0 < 14; ++t0)
            stencil_row(&ps[buf][li + t0][lj + 2], t0, w, acc);
        buf ^= 1;
    }
    #undef BWD_FILL

    float* gout = d_g + (size_t)fc * NB * GP * GP + (size_t)b * GP * GP;
    #pragma unroll
    for (int i = 0; i < 8; ++i) {
        int m = m0 + li + i;
        int n = n0 + lj;
        if (m < GP) {
            if (n + 1 < GP) {
                *reinterpret_cast<float2*>(gout + m * GP + n) =
                    make_float2(acc[i][0], acc[i][1]);
            } else if (n < GP) {
                gout[m * GP + n] = acc[i][0];
            }
        }
    }
}

// ---------------- kernel D: fold + residual + prox ----------------
__global__ void finish_kernel(const float* __restrict__ input,
                              const float* __restrict__ noisy,
                              const float* __restrict__ a_cond,
                              float* __restrict__ out)
{
    int t = blockIdx.x * blockDim.x + threadIdx.x;
    if (t >= NB * NH * NW) return;
    int b   = t >> 16;
    int rem = t & 65535;
    int i = rem >> 8, j = rem & 255;

    const float* gb0 = d_g + (size_t)b * GP * GP;
    const float* gb1 = gb0 + (size_t)NB * GP * GP;

    int mi[2], nj[2];
    int nm = 1, nn = 1;
    mi[0] = i + 3;
    nj[0] = j + 3;
    if (i < 3)       mi[nm++] = 2 - i;
    if (i >= NH - 3) mi[nm++] = 2 * NH + 2 - i;
    if (j < 3)       nj[nn++] = 2 - j;
    if (j >= NW - 3) nj[nn++] = 2 * NW + 2 - j;

    float r = 0.f;
    for (int a = 0; a < nm; ++a)
        for (int c = 0; c < nn; ++c) {
            int off = mi[a] * GP + nj[c];
            r += gb0[off] + gb1[off];
        }

    float av = a_cond[b];
    float z = input[t] - r;
    float d = z - av;
    out[t] = 0.5f * (d + sqrtf(d * d + 4.0f * av * noisy[t]));
}

// ---------------- launch ----------------
extern "C" void kernel_launch(void* const* d_in, const int* in_sizes, int n_in,
                              void* d_out, int out_size)
{
    const float* input   = (const float*)d_in[0];
    const float* noisy   = (const float*)d_in[1];
    const float* a_cond  = (const float*)d_in[2];
    const float* cw      = (const float*)d_in[3];
    const float* sf      = (const float*)d_in[4];
    const float* rw      = (const float*)d_in[5];
    const float* centers = (const float*)d_in[6];
    const float* grid    = (const float*)d_in[7];
    float* out = (float*)d_out;

    prep_weights<<<1, 64>>>(cw, sf, grid);
    prep_table<<<NF, 128>>>(rw, centers, grid);
    fwd_kernel<<<dim3(8, 8, NB), 128>>>(input);
    bwd_kernel<<<dim3(10, 9, NB), 128>>>();
    finish_kernel<<<(NB * NH * NW + 255) / 256, 256>>>(input, noisy, a_cond, out);
}